// round 1
// baseline (speedup 1.0000x reference)
#include <cuda_runtime.h>
#include <cstdint>

// Problem: B=32, N=8192, DIM=256, M=1228
//   in0: x            [B, N, DIM] float32   (67,108,864 elems)
//   in1: mask_indices [B, M]      int32     (39,296 elems)
//   in2: emb_mask     [1, DIM]    float32   (256 elems)
// out: masked_x [B*N*DIM] floats, then (if out_size allows) mask_indices as floats.

#define DIM 256

// One block per masked row. 64 threads x float4 = 256 floats.
// Thread 0 also writes the float-converted index (second tuple output).
__global__ void scatter_mask_kernel(const int* __restrict__ mask_indices,
                                    const float* __restrict__ emb_mask,
                                    float* __restrict__ out,
                                    float* __restrict__ out_idx,  // may be null
                                    int M, int N)
{
    int row = blockIdx.x;              // 0 .. B*M-1
    int b   = row / M;
    int idx = mask_indices[row];       // 0 .. N-1 (unique per batch row)

    // Destination row in out
    float4* dst = reinterpret_cast<float4*>(
        out + ((size_t)b * N + (size_t)idx) * DIM);

    // Broadcast emb row (L2-resident, 1 KB)
    const float4* src = reinterpret_cast<const float4*>(emb_mask);
    dst[threadIdx.x] = src[threadIdx.x];

    if (out_idx != nullptr && threadIdx.x == 0) {
        out_idx[row] = (float)idx;     // indices <= 8191: exact in fp32
    }
}

extern "C" void kernel_launch(void* const* d_in, const int* in_sizes, int n_in,
                              void* d_out, int out_size)
{
    const float* x            = (const float*)d_in[0];
    const int*   mask_indices = (const int*)d_in[1];
    const float* emb_mask     = (const float*)d_in[2];
    float*       out          = (float*)d_out;

    const int x_elems   = in_sizes[0];         // B*N*DIM
    const int idx_elems = in_sizes[1];         // B*M
    const int BN        = x_elems / DIM;       // B*N
    // Infer B from index count assuming M = 1228; but derive robustly:
    // mask_indices is [B, M]; x is [B, N, DIM] with N*DIM rows per batch.
    // We know N = 8192 for this problem; keep it parametric where cheap.
    const int N = 8192;
    const int B = BN / N;
    const int M = idx_elems / B;

    // 1) Bulk copy x -> out (device-to-device, async, graph-capturable)
    cudaMemcpyAsync(out, x, (size_t)x_elems * sizeof(float),
                    cudaMemcpyDeviceToDevice, 0);

    // 2) Scatter emb_mask into masked rows + emit indices (second output)
    float* out_idx = (out_size >= x_elems + idx_elems)
                   ? (out + x_elems) : nullptr;

    scatter_mask_kernel<<<B * M, DIM / 4, 0, 0>>>(
        mask_indices, emb_mask, out, out_idx, M, N);
}

// round 2
// speedup vs baseline: 1.0907x; 1.0907x over previous
#include <cuda_runtime.h>
#include <cstdint>

// Problem: B=32, N=8192, DIM=256, M=1228
//   in0: x            [B, N, DIM] float32
//   in1: mask_indices [B, M]      int32
//   in2: emb_mask     [1, DIM]    float32
// out: masked_x [B*N*DIM] floats (+ mask_indices as floats if room).

#define DIM   256
#define BN_MAX (32 * 8192)

// Per-row mask flag. 256 KB, L2-resident during the fused pass.
__device__ unsigned char g_flags[BN_MAX];

__global__ void clear_flags_kernel(int bn_words)  // bn_words = BN/16
{
    int i = blockIdx.x * blockDim.x + threadIdx.x;
    if (i < bn_words)
        reinterpret_cast<uint4*>(g_flags)[i] = make_uint4(0, 0, 0, 0);
}

__global__ void set_flags_kernel(const int* __restrict__ mask_indices,
                                 float* __restrict__ out_idx,  // may be null
                                 int BM, int M, int N)
{
    int i = blockIdx.x * blockDim.x + threadIdx.x;
    if (i >= BM) return;
    int b   = i / M;
    int idx = mask_indices[i];
    g_flags[b * N + idx] = 1;
    if (out_idx != nullptr)
        out_idx[i] = (float)idx;      // indices < 8192: exact in fp32
}

// 256 threads/block, 4 rows/block (64 threads x float4 per row).
// Masked rows: write emb_mask, SKIP the x load entirely.
__global__ void __launch_bounds__(256)
fused_copy_kernel(const float* __restrict__ x,
                  const float* __restrict__ emb_mask,
                  float* __restrict__ out,
                  int BN)
{
    const int tid   = threadIdx.x;
    const int row   = blockIdx.x * 4 + (tid >> 6);   // global row in [0, BN)
    const int col4  = tid & 63;                      // float4 index within row
    if (row >= BN) return;

    const size_t off = (size_t)row * (DIM / 4) + col4;
    float4* dst = reinterpret_cast<float4*>(out) + off;

    if (g_flags[row]) {
        // emb_mask: 1 KB, hot in L1 after first touch
        dst[0] = reinterpret_cast<const float4*>(emb_mask)[col4];
    } else {
        dst[0] = reinterpret_cast<const float4*>(x)[off];
    }
}

extern "C" void kernel_launch(void* const* d_in, const int* in_sizes, int n_in,
                              void* d_out, int out_size)
{
    const float* x            = (const float*)d_in[0];
    const int*   mask_indices = (const int*)d_in[1];
    const float* emb_mask     = (const float*)d_in[2];
    float*       out          = (float*)d_out;

    const int x_elems   = in_sizes[0];          // B*N*DIM
    const int idx_elems = in_sizes[1];          // B*M
    const int BN        = x_elems / DIM;        // B*N
    const int N         = 8192;
    const int B         = BN / N;
    const int M         = idx_elems / B;

    float* out_idx = (out_size >= x_elems + idx_elems)
                   ? (out + x_elems) : nullptr;

    // 1) Clear flags (256 KB -> 16K uint4 stores)
    const int bn_words = BN / 16;
    clear_flags_kernel<<<(bn_words + 255) / 256, 256>>>(bn_words);

    // 2) Set flags from indices + emit float indices
    set_flags_kernel<<<(idx_elems + 255) / 256, 256>>>(
        mask_indices, out_idx, idx_elems, M, N);

    // 3) Fused select-copy over all rows
    fused_copy_kernel<<<(BN + 3) / 4, 256>>>(x, emb_mask, out, BN);
}

// round 3
// speedup vs baseline: 1.2000x; 1.1002x over previous
#include <cuda_runtime.h>
#include <cstdint>

// Problem: B=32, N=8192, DIM=256, M=1228
//   in0: x            [B, N, DIM] float32
//   in1: mask_indices [B, M]      int32
//   in2: emb_mask     [1, DIM]    float32
// out: masked_x [B*N*DIM] floats (+ mask_indices as floats if room).

#define DIM      256
#define ROWS_PB  256    // rows handled per block (divides N)
#define THREADS  256

// Single fused kernel:
//  - block b_blk handles rows [r0, r0+ROWS_PB) of batch b
//  - scan batch's mask indices -> smem flags for in-range rows
//  - select-copy: masked rows write emb (x load skipped), others copy x
//  - first block of each batch also emits float-converted indices
__global__ void __launch_bounds__(THREADS)
fused_mask_kernel(const float* __restrict__ x,
                  const int*   __restrict__ mask_indices,
                  const float* __restrict__ emb_mask,
                  float*       __restrict__ out,
                  float*       __restrict__ out_idx,   // may be null
                  int M, int N, int blocks_per_batch)
{
    __shared__ unsigned char flags[ROWS_PB];

    const int tid   = threadIdx.x;
    const int b     = blockIdx.x / blocks_per_batch;
    const int blk   = blockIdx.x % blocks_per_batch;
    const int r0    = blk * ROWS_PB;                  // first row (within batch)

    // clear smem flags
    flags[tid] = 0;

    __syncthreads();   // (flags[tid]=0 by same tid that reads? no — scan writes any)

    // scan this batch's indices; mark rows in our range
    const int* idx_row = mask_indices + (size_t)b * M;
    for (int i = tid; i < M; i += THREADS) {
        int idx = idx_row[i];
        int local = idx - r0;
        if ((unsigned)local < (unsigned)ROWS_PB)
            flags[local] = 1;
        if (blk == 0 && out_idx != nullptr)
            out_idx[(size_t)b * M + i] = (float)idx;  // idx < 8192: exact in fp32
    }
    __syncthreads();

    // select-copy: 4 rows per iteration (64 threads x float4 per row)
    const int sub  = tid >> 6;        // 0..3: row within group of 4
    const int col4 = tid & 63;        // float4 lane within row

    // emb row held in a register (1 KB, broadcast)
    const float4 emb = reinterpret_cast<const float4*>(emb_mask)[col4];

    const size_t base = ((size_t)b * N + r0) * (DIM / 4);
    const float4* __restrict__ src = reinterpret_cast<const float4*>(x) + base;
    float4*       __restrict__ dst = reinterpret_cast<float4*>(out)     + base;

    #pragma unroll 4
    for (int it = 0; it < ROWS_PB / 4; ++it) {
        const int row_local = it * 4 + sub;
        const size_t off = (size_t)row_local * (DIM / 4) + col4;
        // warp-uniform branch: each warp covers a single row
        if (flags[row_local]) {
            dst[off] = emb;
        } else {
            dst[off] = src[off];
        }
    }
}

extern "C" void kernel_launch(void* const* d_in, const int* in_sizes, int n_in,
                              void* d_out, int out_size)
{
    const float* x            = (const float*)d_in[0];
    const int*   mask_indices = (const int*)d_in[1];
    const float* emb_mask     = (const float*)d_in[2];
    float*       out          = (float*)d_out;

    const int x_elems   = in_sizes[0];          // B*N*DIM
    const int idx_elems = in_sizes[1];          // B*M
    const int BN        = x_elems / DIM;        // B*N
    const int N         = 8192;
    const int B         = BN / N;
    const int M         = idx_elems / B;

    float* out_idx = (out_size >= x_elems + idx_elems)
                   ? (out + x_elems) : nullptr;

    const int blocks_per_batch = N / ROWS_PB;   // 32
    fused_mask_kernel<<<B * blocks_per_batch, THREADS>>>(
        x, mask_indices, emb_mask, out, out_idx, M, N, blocks_per_batch);
}

// round 4
// speedup vs baseline: 1.2919x; 1.0766x over previous
#include <cuda_runtime.h>
#include <cstdint>

// Problem: B=32, N=8192, DIM=256, M=1228
//   in0: x            [B, N, DIM] float32
//   in1: mask_indices [B, M]      int32
//   in2: emb_mask     [1, DIM]    float32
// out: masked_x [B*N*DIM] floats (+ mask_indices as floats if room).

#define DIM      256
#define ROWS_PB  256    // rows per block (divides N); 256 flags = 8 uint32
#define THREADS  256
#define UNROLL   8

__global__ void __launch_bounds__(THREADS)
fused_mask_kernel(const float* __restrict__ x,
                  const int*   __restrict__ mask_indices,
                  const float* __restrict__ emb_mask,
                  float*       __restrict__ out,
                  float*       __restrict__ out_idx,   // may be null
                  int M, int N, int blocks_per_batch)
{
    __shared__ uint32_t fl[ROWS_PB / 32];   // 8 words: bitmask of masked rows

    const int tid = threadIdx.x;
    const int b   = blockIdx.x / blocks_per_batch;
    const int blk = blockIdx.x % blocks_per_batch;
    const int r0  = blk * ROWS_PB;

    if (tid < ROWS_PB / 32) fl[tid] = 0;
    __syncthreads();

    // scan this batch's indices; set bits for rows in our range
    const int* idx_row = mask_indices + (size_t)b * M;
    for (int i = tid; i < M; i += THREADS) {
        int idx   = idx_row[i];
        int local = idx - r0;
        if ((unsigned)local < (unsigned)ROWS_PB)
            atomicOr(&fl[local >> 5], 1u << (local & 31));
        if (blk == 0 && out_idx != nullptr)
            out_idx[(size_t)b * M + i] = (float)idx;  // idx < 8192: exact in fp32
    }
    __syncthreads();

    // pull the whole bitmask into registers (broadcast LDS, conflict-free)
    uint32_t fw[ROWS_PB / 32];
    #pragma unroll
    for (int w = 0; w < ROWS_PB / 32; ++w) fw[w] = fl[w];

    const int sub  = tid >> 6;        // 0..3: row lane within a group of 4 rows
    const int col4 = tid & 63;        // float4 lane within row

    const float4 emb = reinterpret_cast<const float4*>(emb_mask)[col4];

    const size_t base = ((size_t)b * N + r0) * (DIM / 4);
    const float4* __restrict__ src = reinterpret_cast<const float4*>(x) + base;
    float4*       __restrict__ dst = reinterpret_cast<float4*>(out)     + base;

    // 64 row-iterations per thread, batched 8 at a time for MLP
    #pragma unroll
    for (int it = 0; it < ROWS_PB / 4; it += UNROLL) {
        float4 v[UNROLL];
        // phase 1: issue all loads (masked rows take emb, skip the LDG)
        #pragma unroll
        for (int u = 0; u < UNROLL; ++u) {
            const int row = (it + u) * 4 + sub;
            const size_t off = (size_t)row * (DIM / 4) + col4;
            const bool masked = (fw[row >> 5] >> (row & 31)) & 1u;
            v[u] = masked ? emb : __ldcs(&src[off]);
        }
        // phase 2: stores (streaming, evict-first)
        #pragma unroll
        for (int u = 0; u < UNROLL; ++u) {
            const int row = (it + u) * 4 + sub;
            const size_t off = (size_t)row * (DIM / 4) + col4;
            __stcs(&dst[off], v[u]);
        }
    }
}

extern "C" void kernel_launch(void* const* d_in, const int* in_sizes, int n_in,
                              void* d_out, int out_size)
{
    const float* x            = (const float*)d_in[0];
    const int*   mask_indices = (const int*)d_in[1];
    const float* emb_mask     = (const float*)d_in[2];
    float*       out          = (float*)d_out;

    const int x_elems   = in_sizes[0];          // B*N*DIM
    const int idx_elems = in_sizes[1];          // B*M
    const int BN        = x_elems / DIM;        // B*N
    const int N         = 8192;
    const int B         = BN / N;
    const int M         = idx_elems / B;

    float* out_idx = (out_size >= x_elems + idx_elems)
                   ? (out + x_elems) : nullptr;

    const int blocks_per_batch = N / ROWS_PB;   // 32
    fused_mask_kernel<<<B * blocks_per_batch, THREADS>>>(
        x, mask_indices, emb_mask, out, out_idx, M, N, blocks_per_batch);
}

// round 5
// speedup vs baseline: 1.3083x; 1.0127x over previous
#include <cuda_runtime.h>
#include <cstdint>

// Problem: B=32, N=8192, DIM=256, M=1228
//   in0: x            [B, N, DIM] float32
//   in1: mask_indices [B, M]      int32
//   in2: emb_mask     [1, DIM]    float32
// out: masked_x [B*N*DIM] floats (+ mask_indices as floats if room).

#define DIM      256
#define ROWS_PB  256    // rows per block (divides N); 256 flags = 8 uint32
#define THREADS  256
#define UNROLL   4      // staging regs: 4 x float4 = 16 regs

__global__ void __launch_bounds__(THREADS)
fused_mask_kernel(const float* __restrict__ x,
                  const int*   __restrict__ mask_indices,
                  const float* __restrict__ emb_mask,
                  float*       __restrict__ out,
                  float*       __restrict__ out_idx,   // may be null
                  int M, int N, int blocks_per_batch)
{
    __shared__ uint32_t fl[ROWS_PB / 32];   // bitmask of masked rows

    const int tid = threadIdx.x;
    const int b   = blockIdx.x / blocks_per_batch;
    const int blk = blockIdx.x % blocks_per_batch;
    const int r0  = blk * ROWS_PB;

    if (tid < ROWS_PB / 32) fl[tid] = 0;
    __syncthreads();

    // scan this batch's indices; set bits for rows in our range
    const int* idx_row = mask_indices + (size_t)b * M;
    for (int i = tid; i < M; i += THREADS) {
        int idx   = idx_row[i];
        int local = idx - r0;
        if ((unsigned)local < (unsigned)ROWS_PB)
            atomicOr(&fl[local >> 5], 1u << (local & 31));
        if (blk == 0 && out_idx != nullptr)
            out_idx[(size_t)b * M + i] = (float)idx;  // idx < 8192: exact in fp32
    }
    __syncthreads();

    // pull the whole bitmask into registers (broadcast LDS, conflict-free)
    uint32_t fw[ROWS_PB / 32];
    #pragma unroll
    for (int w = 0; w < ROWS_PB / 32; ++w) fw[w] = fl[w];

    const int sub  = tid >> 6;        // 0..3: row lane within a group of 4 rows
    const int col4 = tid & 63;        // float4 lane within row

    const float4 emb = reinterpret_cast<const float4*>(emb_mask)[col4];

    const size_t base = ((size_t)b * N + r0) * (DIM / 4);
    const float4* __restrict__ src = reinterpret_cast<const float4*>(x) + base;
    float4*       __restrict__ dst = reinterpret_cast<float4*>(out)     + base;

    // 64 row-iterations per thread; software-pipelined groups of UNROLL
    constexpr int NIT    = ROWS_PB / 4;          // 64
    constexpr int GROUPS = NIT / UNROLL;         // 16

    float4 v[UNROLL];

    // prologue: load group 0
    #pragma unroll
    for (int u = 0; u < UNROLL; ++u) {
        const int row = u * 4 + sub;
        const size_t off = (size_t)row * (DIM / 4) + col4;
        const bool masked = (fw[row >> 5] >> (row & 31)) & 1u;
        v[u] = masked ? emb : __ldcs(&src[off]);
    }

    #pragma unroll
    for (int g = 0; g < GROUPS; ++g) {
        float4 nxt[UNROLL];
        if (g + 1 < GROUPS) {
            // prefetch next group while current stores drain
            #pragma unroll
            for (int u = 0; u < UNROLL; ++u) {
                const int row = ((g + 1) * UNROLL + u) * 4 + sub;
                const size_t off = (size_t)row * (DIM / 4) + col4;
                const bool masked = (fw[row >> 5] >> (row & 31)) & 1u;
                nxt[u] = masked ? emb : __ldcs(&src[off]);
            }
        }
        // store current group (streaming, evict-first)
        #pragma unroll
        for (int u = 0; u < UNROLL; ++u) {
            const int row = (g * UNROLL + u) * 4 + sub;
            const size_t off = (size_t)row * (DIM / 4) + col4;
            __stcs(&dst[off], v[u]);
        }
        #pragma unroll
        for (int u = 0; u < UNROLL; ++u) v[u] = nxt[u];
    }
}

extern "C" void kernel_launch(void* const* d_in, const int* in_sizes, int n_in,
                              void* d_out, int out_size)
{
    const float* x            = (const float*)d_in[0];
    const int*   mask_indices = (const int*)d_in[1];
    const float* emb_mask     = (const float*)d_in[2];
    float*       out          = (float*)d_out;

    const int x_elems   = in_sizes[0];          // B*N*DIM
    const int idx_elems = in_sizes[1];          // B*M
    const int BN        = x_elems / DIM;        // B*N
    const int N         = 8192;
    const int B         = BN / N;
    const int M         = idx_elems / B;

    float* out_idx = (out_size >= x_elems + idx_elems)
                   ? (out + x_elems) : nullptr;

    const int blocks_per_batch = N / ROWS_PB;   // 32
    fused_mask_kernel<<<B * blocks_per_batch, THREADS>>>(
        x, mask_indices, emb_mask, out, out_idx, M, N, blocks_per_batch);
}